// round 2
// baseline (speedup 1.0000x reference)
#include <cuda_runtime.h>
#include <math.h>

// Problem constants
#define BB   8
#define NN   1024
#define CC   1024
#define HH   16
#define HD   64
#define NTASKS 10
#define NFRQ   3000
#define ROWS (BB*NN)          // 8192
#define QKVC (3*CC)           // 3072

// Scratch (device globals: allocation-free)
__device__ float g_qkv[ROWS*QKVC];     // 96 MB  (q|k|v column blocks)
__device__ float g_dct[CC*CC];         // 4 MB
__device__ float g_Sk [CC*CC];
__device__ float g_Sv [CC*CC];
__device__ float g_tmp[CC*CC];
__device__ float g_Wk [CC*CC];
__device__ float g_Wv [CC*CC];
__device__ float g_ctx[ROWS*CC];       // 32 MB

// ---------------------------------------------------------------------------
// Zero the scatter planes (needed every call: graph replays)
__global__ void zero_S_kernel() {
    int i = blockIdx.x * blockDim.x + threadIdx.x;
    if (i < CC*CC) { g_Sk[i] = 0.f; g_Sv[i] = 0.f; }
}

// Scatter-add per-task frequency coefficients (tasks 0..task)
__global__ void scatter_kernel(const float* __restrict__ coef_k,
                               const float* __restrict__ coef_v,
                               const int*   __restrict__ indices,
                               const int*   __restrict__ task) {
    int i = blockIdx.x * blockDim.x + threadIdx.x;
    if (i >= NTASKS * NFRQ) return;
    int t = i / NFRQ;
    if (t > *task) return;
    int idx = indices[i];
    atomicAdd(&g_Sk[idx], coef_k[i]);
    atomicAdd(&g_Sv[idx], coef_v[i]);
}

// Orthonormal DCT-II matrix. Angle arithmetic replicates jax fp32 exactly:
// ((pi_f32 * i) * (2j+1)) / 2048, then accurate cos (double) of that fp32 value.
__global__ void dct_kernel() {
    int idx = blockIdx.x * blockDim.x + threadIdx.x;
    if (idx >= CC*CC) return;
    int i = idx >> 10, j = idx & 1023;
    float v;
    if (i == 0) {
        v = 0.03125f;                      // sqrt(1/1024) exact
    } else {
        const float pif = 3.14159265358979323846f;   // rounds to f32 pi
        float ang = pif * (float)i;
        ang = ang * (float)(2*j + 1);
        ang = ang / 2048.0f;
        float c = (float)cos((double)ang);           // accurate, fast-math-proof
        v = (float)sqrt(2.0/1024.0) * c;
    }
    g_dct[idx] = v;
}

// ---------------------------------------------------------------------------
// Generic tiled SGEMM: C[M,N] = op(A) @ op(B) (+ C) (+ bias)
//   TRANSA: a(m,k) = A[k*lda + m]  else A[m*lda + k]
//   TRANSB: b(k,n) = B[n*ldb + k]  else B[k*ldb + n]
// Tile 64x64x16, 256 threads, 4x4 per thread. All dims multiples of 64/16.
template<int TRANSA, int TRANSB>
__global__ __launch_bounds__(256)
void gemm_kernel(int M, int N, int K,
                 const float* __restrict__ A, int lda,
                 const float* __restrict__ B, int ldb,
                 float* __restrict__ C, int ldc,
                 int accumulate, const float* __restrict__ bias) {
    __shared__ float As[16][68];
    __shared__ float Bs[16][68];
    const int t  = threadIdx.x;
    const int tx = t & 15, ty = t >> 4;
    const int m0 = blockIdx.y * 64, n0 = blockIdx.x * 64;

    float acc[4][4] = {};
    for (int k0 = 0; k0 < K; k0 += 16) {
        #pragma unroll
        for (int r = 0; r < 4; r++) {
            int idx = r * 256 + t;
            if (TRANSA) {
                int mm = idx & 63, kk = idx >> 6;
                As[kk][mm] = A[(size_t)(k0 + kk) * lda + m0 + mm];
            } else {
                int kk = idx & 15, mm = idx >> 4;
                As[kk][mm] = A[(size_t)(m0 + mm) * lda + k0 + kk];
            }
        }
        #pragma unroll
        for (int r = 0; r < 4; r++) {
            int idx = r * 256 + t;
            if (TRANSB) {
                int kk = idx & 15, nn = idx >> 4;
                Bs[kk][nn] = B[(size_t)(n0 + nn) * ldb + k0 + kk];
            } else {
                int nn = idx & 63, kk = idx >> 6;
                Bs[kk][nn] = B[(size_t)(k0 + kk) * ldb + n0 + nn];
            }
        }
        __syncthreads();
        #pragma unroll
        for (int kk = 0; kk < 16; kk++) {
            float4 a4 = *(const float4*)&As[kk][ty * 4];
            float4 b4 = *(const float4*)&Bs[kk][tx * 4];
            float ra[4] = {a4.x, a4.y, a4.z, a4.w};
            float rb[4] = {b4.x, b4.y, b4.z, b4.w};
            #pragma unroll
            for (int i = 0; i < 4; i++)
                #pragma unroll
                for (int j = 0; j < 4; j++)
                    acc[i][j] += ra[i] * rb[j];
        }
        __syncthreads();
    }
    #pragma unroll
    for (int i = 0; i < 4; i++) {
        int m = m0 + ty * 4 + i;
        #pragma unroll
        for (int j = 0; j < 4; j++) {
            int n = n0 + tx * 4 + j;
            float v = acc[i][j];
            if (bias)       v += bias[n];
            size_t o = (size_t)m * ldc + n;
            if (accumulate) v += C[o];
            C[o] = v;
        }
    }
}

// ---------------------------------------------------------------------------
// Flash-style attention. One block = 64 queries of one (b,h). Each thread owns
// one query row: q & acc in registers, K/V tiles in padded smem (broadcast
// reads), online softmax with rescale-on-new-max.
__global__ __launch_bounds__(64)
void attn_kernel() {
    __shared__ float Ks[64][68];
    __shared__ float Vs[64][68];
    const int tid = threadIdx.x;
    const int bh  = blockIdx.y;
    const int b = bh >> 4, h = bh & 15;
    const int n = blockIdx.x * 64 + tid;

    const float* qrow = g_qkv + (size_t)(b * NN + n) * QKVC + h * HD;
    float qv[HD];
    #pragma unroll
    for (int d4 = 0; d4 < 16; d4++) {
        float4 q4 = *(const float4*)(qrow + d4 * 4);
        qv[d4*4+0] = q4.x * 0.125f;  // scale = hd^-0.5 folded into q
        qv[d4*4+1] = q4.y * 0.125f;
        qv[d4*4+2] = q4.z * 0.125f;
        qv[d4*4+3] = q4.w * 0.125f;
    }

    float m_run = -INFINITY, l_run = 0.f;
    float acc[HD];
    #pragma unroll
    for (int d = 0; d < HD; d++) acc[d] = 0.f;

    for (int kt = 0; kt < NN / 64; kt++) {
        const float* krow = g_qkv + (size_t)(b * NN + kt * 64 + tid) * QKVC + CC  + h * HD;
        const float* vrow = g_qkv + (size_t)(b * NN + kt * 64 + tid) * QKVC + 2*CC + h * HD;
        #pragma unroll
        for (int d4 = 0; d4 < 16; d4++) {
            *(float4*)&Ks[tid][d4 * 4] = *(const float4*)(krow + d4 * 4);
            *(float4*)&Vs[tid][d4 * 4] = *(const float4*)(vrow + d4 * 4);
        }
        __syncthreads();

        for (int kk = 0; kk < 64; kk++) {
            float s = 0.f;
            #pragma unroll
            for (int d4 = 0; d4 < 16; d4++) {
                float4 k4 = *(const float4*)&Ks[kk][d4 * 4];
                s += qv[d4*4+0]*k4.x + qv[d4*4+1]*k4.y
                   + qv[d4*4+2]*k4.z + qv[d4*4+3]*k4.w;
            }
            if (s > m_run) {
                float corr = expf(m_run - s);   // expf(-inf)=0 handles init
                l_run *= corr;
                #pragma unroll
                for (int d = 0; d < HD; d++) acc[d] *= corr;
                m_run = s;
            }
            float p = expf(s - m_run);
            l_run += p;
            #pragma unroll
            for (int d4 = 0; d4 < 16; d4++) {
                float4 v4 = *(const float4*)&Vs[kk][d4 * 4];
                acc[d4*4+0] += p * v4.x;
                acc[d4*4+1] += p * v4.y;
                acc[d4*4+2] += p * v4.z;
                acc[d4*4+3] += p * v4.w;
            }
        }
        __syncthreads();
    }

    float inv = 1.f / l_run;
    float* orow = g_ctx + (size_t)(b * NN + n) * CC + h * HD;
    #pragma unroll
    for (int d4 = 0; d4 < 16; d4++) {
        float4 o4;
        o4.x = acc[d4*4+0] * inv;
        o4.y = acc[d4*4+1] * inv;
        o4.z = acc[d4*4+2] * inv;
        o4.w = acc[d4*4+3] * inv;
        *(float4*)(orow + d4 * 4) = o4;
    }
}

// ---------------------------------------------------------------------------
extern "C" void kernel_launch(void* const* d_in, const int* in_sizes, int n_in,
                              void* d_out, int out_size) {
    const float* x     = (const float*)d_in[0];  // (8,1024,1024)
    const float* Wqkv  = (const float*)d_in[1];  // (3072,1024)
    const float* Wproj = (const float*)d_in[2];  // (1024,1024)
    const float* bproj = (const float*)d_in[3];  // (1024,)
    const float* coefk = (const float*)d_in[4];  // (10,3000)
    const float* coefv = (const float*)d_in[5];  // (10,3000)
    const int*   indices = (const int*)d_in[6];  // (10,3000)
    const int*   task  = (const int*)d_in[7];    // scalar
    float*       out   = (float*)d_out;          // (8,1024,1024)
    (void)in_sizes; (void)n_in; (void)out_size;

    void *p;
    cudaGetSymbolAddress(&p, g_qkv); float* qkv = (float*)p;
    cudaGetSymbolAddress(&p, g_dct); float* dct = (float*)p;
    cudaGetSymbolAddress(&p, g_Sk);  float* Sk  = (float*)p;
    cudaGetSymbolAddress(&p, g_Sv);  float* Sv  = (float*)p;
    cudaGetSymbolAddress(&p, g_tmp); float* tmp = (float*)p;
    cudaGetSymbolAddress(&p, g_Wk);  float* Wk  = (float*)p;
    cudaGetSymbolAddress(&p, g_Wv);  float* Wv  = (float*)p;
    cudaGetSymbolAddress(&p, g_ctx); float* ctx = (float*)p;

    // 1. qkv = x @ Wqkv^T   (8192 x 3072 x 1024)
    gemm_kernel<0,1><<<dim3(QKVC/64, ROWS/64), 256>>>(
        ROWS, QKVC, CC, x, CC, Wqkv, CC, qkv, QKVC, 0, nullptr);

    // 2. Build DCT-LoRA weights
    zero_S_kernel<<<(CC*CC + 255)/256, 256>>>();
    scatter_kernel<<<(NTASKS*NFRQ + 255)/256, 256>>>(coefk, coefv, indices, task);
    dct_kernel<<<(CC*CC + 255)/256, 256>>>();

    // Wk = Bm^T @ (Sk @ Bm)
    gemm_kernel<0,0><<<dim3(16,16), 256>>>(CC, CC, CC, Sk,  CC, dct, CC, tmp, CC, 0, nullptr);
    gemm_kernel<1,0><<<dim3(16,16), 256>>>(CC, CC, CC, dct, CC, tmp, CC, Wk,  CC, 0, nullptr);
    // Wv = Bm^T @ (Sv @ Bm)
    gemm_kernel<0,0><<<dim3(16,16), 256>>>(CC, CC, CC, Sv,  CC, dct, CC, tmp, CC, 0, nullptr);
    gemm_kernel<1,0><<<dim3(16,16), 256>>>(CC, CC, CC, dct, CC, tmp, CC, Wv,  CC, 0, nullptr);

    // 3. k += x @ Wk^T ; v += x @ Wv^T (accumulate into qkv column blocks)
    gemm_kernel<0,1><<<dim3(16, ROWS/64), 256>>>(
        ROWS, CC, CC, x, CC, Wk, CC, qkv + CC,   QKVC, 1, nullptr);
    gemm_kernel<0,1><<<dim3(16, ROWS/64), 256>>>(
        ROWS, CC, CC, x, CC, Wv, CC, qkv + 2*CC, QKVC, 1, nullptr);

    // 4. attention -> ctx (B,N,H*hd)
    attn_kernel<<<dim3(NN/64, BB*HH), 64>>>();

    // 5. out = ctx @ Wproj^T + b
    gemm_kernel<0,1><<<dim3(16, ROWS/64), 256>>>(
        ROWS, CC, CC, ctx, CC, Wproj, CC, out, CC, 0, bproj);
}